// round 17
// baseline (speedup 1.0000x reference)
#include <cuda_runtime.h>
#include <cuda_pipeline_primitives.h>
#include <math.h>

#define H 160           // B*G = 4*40 heads
#define C 13
#define T 1024
#define F 513           // rfft bins
#define FP 514          // padded K/V row pitch (float2) -> 16B-aligned rows
#define NSIG (H * C)    // 2080 signals

typedef unsigned long long ull;

// ---------------- f32x2 packed math helpers (sm_103a FFMA2) ----------------
__device__ __forceinline__ ull pk2(float a, float b) {
    ull r;
    asm("mov.b64 %0, {%1, %2};" : "=l"(r) : "r"(__float_as_uint(a)), "r"(__float_as_uint(b)));
    return r;
}
__device__ __forceinline__ void upk2(ull v, float& a, float& b) {
    unsigned lo, hi;
    asm("mov.b64 {%0, %1}, %2;" : "=r"(lo), "=r"(hi) : "l"(v));
    a = __uint_as_float(lo);
    b = __uint_as_float(hi);
}
__device__ __forceinline__ ull fma2(ull a, ull b, ull c) {
    ull d;
    asm("fma.rn.f32x2 %0, %1, %2, %3;" : "=l"(d) : "l"(a), "l"(b), "l"(c));
    return d;
}
__device__ __forceinline__ ull add2(ull a, ull b) {
    ull d;
    asm("add.rn.f32x2 %0, %1, %2;" : "=l"(d) : "l"(a), "l"(b));
    return d;
}
__device__ __forceinline__ ull shfl_xor_ull(ull v, int m) {
    unsigned lo, hi;
    asm("mov.b64 {%0, %1}, %2;" : "=r"(lo), "=r"(hi) : "l"(v));
    lo = __shfl_xor_sync(0xffffffffu, lo, m);
    hi = __shfl_xor_sync(0xffffffffu, hi, m);
    ull r;
    asm("mov.b64 %0, {%1, %2};" : "=l"(r) : "r"(lo), "r"(hi));
    return r;
}
__device__ __forceinline__ float sqrt_approx(float x) {
    float r;
    asm("sqrt.approx.f32 %0, %1;" : "=f"(r) : "f"(x));
    return r;
}

// ---------------- scratch (device globals: allowed; no runtime alloc) ------
__device__ float2 d_W[512];        // twiddles exp(-2*pi*i*k/1024)
__device__ float2 d_X[H * C * F];  // spectrum, layout [head][c][f]
__device__ float2 d_Q[H * C * F];
__device__ __align__(16) float2 d_K[H * C * FP];  // padded pitch, 16B rows
__device__ __align__(16) float2 d_V[H * C * FP];
__device__ float2 d_O[H * C * F];

// flash partials, ull-packed. Per (head, rowgroup, split) record = 56 ull:
//   c*4 + u, u = 0:{r0,r1} 1:{i0,i1} 2:{r2,r3} 3:{i2,i3}    (c = 0..12)
//   52:{m0,m1} 53:{m2,m3} 54:{l0,l1} 55:{l2,l3}
#define NRG 136        // rowgroups with valid rows (136*4 >= 513)
#define NRGP 144       // padded rowgroups (9 row-blocks * 16 warps)
#define NSPLIT 5
#define KT 128         // cols per split: splits {128,128,128,128,1 (+pad)}
#define KTP 128
__device__ ull d_P[(size_t)H * NRGP * NSPLIT * 56];   // ~51.6 MB

// ---------------- twiddle init (double trig for precision) -----------------
__global__ void init_twiddles() {
    int k = threadIdx.x;  // 0..511
    double ang = -2.0 * 3.14159265358979323846 * (double)k / 1024.0;
    d_W[k] = make_float2((float)cos(ang), (float)sin(ang));
}

// ---------------- shared radix-2 DIT FFT core (1024 pts, 512 threads) ------
__device__ __forceinline__ void fft_stages(float2* a, bool inverse) {
    int tid = threadIdx.x;
#pragma unroll
    for (int s = 1; s <= 10; ++s) {
        __syncthreads();
        int half = 1 << (s - 1);
        int k = tid & (half - 1);
        int i0 = ((tid >> (s - 1)) << s) + k;
        float2 w = d_W[k << (10 - s)];
        if (inverse) w.y = -w.y;
        float2 u = a[i0];
        float2 v = a[i0 + half];
        float tr = w.x * v.x - w.y * v.y;
        float ti = w.x * v.y + w.y * v.x;
        a[i0]        = make_float2(u.x + tr, u.y + ti);
        a[i0 + half] = make_float2(u.x - tr, u.y - ti);
    }
    __syncthreads();
}

// ---------------- forward rfft: x[sig][0..1023] -> d_X[sig][0..512] --------
__global__ void fft_forward(const float* __restrict__ x) {
    __shared__ float2 a[1024];
    int sig = blockIdx.x;   // head*13 + c
    int tid = threadIdx.x;  // 0..511
    const float* xp = x + sig * 1024;
    a[__brev(tid) >> 22]       = make_float2(xp[tid], 0.f);
    a[__brev(tid + 512) >> 22] = make_float2(xp[tid + 512], 0.f);
    fft_stages(a, false);
    float2* Xp = d_X + sig * F;
    Xp[tid] = a[tid];
    if (tid == 0) Xp[512] = a[512];
}

// ---------------- QKV: [head][c][f] = sum_cin X[head][cin][f] * W[cin][c] --
// Q written with pitch F; K,V with padded pitch FP (16B-aligned rows).
__global__ void qkv_kernel(const float* __restrict__ wq,
                           const float* __restrict__ wk,
                           const float* __restrict__ wv) {
    __shared__ float ws[3][169];
    int tid = threadIdx.x;
    if (tid < 169) {
        ws[0][tid] = wq[tid];
        ws[1][tid] = wk[tid];
        ws[2][tid] = wv[tid];
    }
    __syncthreads();
    int head = blockIdx.y;
    int f = blockIdx.x * blockDim.x + tid;
    if (f >= F) return;
    float xr[13], xi[13];
#pragma unroll
    for (int c = 0; c < 13; ++c) {
        float2 v = d_X[(head * 13 + c) * F + f];
        xr[c] = v.x;
        xi[c] = v.y;
    }
#pragma unroll 1
    for (int co = 0; co < 13; ++co) {
        float qr = 0.f, qi = 0.f, kr = 0.f, ki = 0.f, vr = 0.f, vi = 0.f;
#pragma unroll
        for (int ci = 0; ci < 13; ++ci) {
            float a = ws[0][ci * 13 + co];
            qr = fmaf(xr[ci], a, qr); qi = fmaf(xi[ci], a, qi);
            float b = ws[1][ci * 13 + co];
            kr = fmaf(xr[ci], b, kr); ki = fmaf(xi[ci], b, ki);
            float g = ws[2][ci * 13 + co];
            vr = fmaf(xr[ci], g, vr); vi = fmaf(xi[ci], g, vi);
        }
        d_Q[(head * 13 + co) * F + f]  = make_float2(qr, qi);
        d_K[(head * 13 + co) * FP + f] = make_float2(kr, ki);
        d_V[(head * 13 + co) * FP + f] = make_float2(vr, vi);
    }
}

// ---------------- attention (split-column flash, register scores) ----------
// CTA = 64 rows x <=128 cols of one head; 16 warps x 4 rows each (512 thr).
// Uneven splits {128,128,128,128,1}: splits 0-3 are mask-free dense tiles.
// Warps whose rows are all >= F exit right after the single __syncthreads.
// K/V tile via 16B-granule cp.async (FP-pitch 16B rows). Lane owns 4
// contiguous cols -> LDS.128 pairs. Value-halving butterfly reductions.
__global__ __launch_bounds__(512, 2) void attn_kernel() {
    __shared__ __align__(16) float2 ksm[13 * KTP];    // 13312 B
    __shared__ __align__(16) float2 vsm[13 * KTP];    // 13312 B
    __shared__ __align__(16) ull    qpk[16 * 13 * 4]; //  6656 B

    int head = blockIdx.y;
    int rb = blockIdx.x / NSPLIT;
    int split = blockIdx.x - rb * NSPLIT;
    int tid = threadIdx.x, lane = tid & 31, w = tid >> 5;  // w = 0..15
    int fbase = rb * 64 + 4 * w;
    int colbase = split * KT;

    // ---- cp.async fill of K,V tile: 16B granules (2 float2 per op) --------
    // chunk m covers cols {2m, 2m+1}; only the F boundary (f=512) splits a
    // chunk (padded FP row makes the 16B read legal; zfill masks pad lane).
    for (int i = tid; i < 13 * (KTP / 2); i += 512) {
        int c = i >> 6, m = i & 63;
        int f2 = colbase + 2 * m;
        size_t zf;
        if (f2 < F)
            zf = (f2 + 1 < F) ? 0 : 8;   // full pair, or zero the 2nd half
        else
            zf = 16;                      // fully out of range -> all zeros
        int go = (head * 13 + c) * FP + ((zf == 16) ? 0 : f2);
        __pipeline_memcpy_async(&ksm[c * KTP + 2 * m], d_K + go, 16, zf);
        __pipeline_memcpy_async(&vsm[c * KTP + 2 * m], d_V + go, 16, zf);
    }
    __pipeline_commit();

    // pack Q rows fbase..fbase+3 (lanes 0..12 handle c=lane)
    if (lane < 13 && fbase < F) {
        const float2* qp = d_Q + (head * 13 + lane) * F + fbase;
        float2 a0 = qp[0];
        float2 a1 = (fbase + 1 < F) ? qp[1] : make_float2(0.f, 0.f);
        float2 a2 = (fbase + 2 < F) ? qp[2] : make_float2(0.f, 0.f);
        float2 a3 = (fbase + 3 < F) ? qp[3] : make_float2(0.f, 0.f);
        ull* dst = qpk + (w * 13 + lane) * 4;
        dst[0] = pk2(a0.x, a1.x);   dst[1] = pk2(a2.x, a3.x);
        dst[2] = pk2(a0.y, a1.y);   dst[3] = pk2(a2.y, a3.y);
    }
    __pipeline_wait_prior(0);
    __syncthreads();

    // rows all out of range -> this warp contributes nothing (only
    // warp-level sync from here on, so returning is safe)
    if (fbase >= F) return;

    const ull Z = pk2(0.f, 0.f);
    const ull SGN = 0x8000000080000000ULL;
    ull sr01[4], sr23[4], si01[4], si23[4];
#pragma unroll
    for (int j = 0; j < 4; ++j) { sr01[j] = sr23[j] = si01[j] = si23[j] = Z; }

    // ---- pass 1: complex dot products (c outer, 4 contiguous cols/lane) ---
#pragma unroll 1
    for (int c = 0; c < 13; ++c) {
        const ulonglong2* qq = (const ulonglong2*)(qpk + (w * 13 + c) * 4);
        ulonglong2 tx = qq[0];  // {qx01, qx23}
        ulonglong2 ty = qq[1];  // {qy01, qy23}
        ull tnx = ty.x ^ SGN;   // {-qy01}
        ull tny = ty.y ^ SGN;   // {-qy23}
        const float4* kp = (const float4*)(ksm + c * KTP + 4 * lane);
        float4 kA = kp[0];   // cols 4lane+0, 4lane+1
        float4 kB = kp[1];   // cols 4lane+2, 4lane+3
        float2 k[4] = { make_float2(kA.x, kA.y), make_float2(kA.z, kA.w),
                        make_float2(kB.x, kB.y), make_float2(kB.z, kB.w) };
#pragma unroll
        for (int j = 0; j < 4; ++j) {
            ull kxx = pk2(k[j].x, k[j].x), kyy = pk2(k[j].y, k[j].y);
            sr01[j] = fma2(tx.x, kxx, sr01[j]);  sr01[j] = fma2(tnx, kyy, sr01[j]);
            sr23[j] = fma2(tx.y, kxx, sr23[j]);  sr23[j] = fma2(tny, kyy, sr23[j]);
            si01[j] = fma2(tx.x, kyy, si01[j]);  si01[j] = fma2(ty.x, kxx, si01[j]);
            si23[j] = fma2(tx.y, kyy, si23[j]);  si23[j] = fma2(ty.y, kxx, si23[j]);
        }
    }

    // ---- magnitudes -> scores (repacked into sr01/sr23), per-lane max -----
    float m0 = 0.f, m1 = 0.f, m2 = 0.f, m3 = 0.f;
#pragma unroll
    for (int j = 0; j < 4; ++j) {
        float r0, r1, r2, r3, u0, u1, u2, u3;
        upk2(sr01[j], r0, r1); upk2(sr23[j], r2, r3);
        upk2(si01[j], u0, u1); upk2(si23[j], u2, u3);
        float sc0 = sqrt_approx(fmaf(r0, r0, u0 * u0));
        float sc1 = sqrt_approx(fmaf(r1, r1, u1 * u1));
        float sc2 = sqrt_approx(fmaf(r2, r2, u2 * u2));
        float sc3 = sqrt_approx(fmaf(r3, r3, u3 * u3));
        m0 = fmaxf(m0, sc0); m1 = fmaxf(m1, sc1);
        m2 = fmaxf(m2, sc2); m3 = fmaxf(m3, sc3);
        sr01[j] = pk2(sc0, sc1); sr23[j] = pk2(sc2, sc3);
    }
#pragma unroll
    for (int o = 16; o; o >>= 1) {
        m0 = fmaxf(m0, __shfl_xor_sync(0xffffffffu, m0, o));
        m1 = fmaxf(m1, __shfl_xor_sync(0xffffffffu, m1, o));
        m2 = fmaxf(m2, __shfl_xor_sync(0xffffffffu, m2, o));
        m3 = fmaxf(m3, __shfl_xor_sync(0xffffffffu, m3, o));
    }

    // ---- p = exp(s - m) (masked only in the last 1-col split) -------------
    float l0 = 0.f, l1 = 0.f, l2 = 0.f, l3 = 0.f;
#pragma unroll
    for (int j = 0; j < 4; ++j) {
        int cl = 4 * lane + j;
        bool valid = (colbase + cl) < F;
        float s0, s1, s2, s3;
        upk2(sr01[j], s0, s1); upk2(sr23[j], s2, s3);
        float p0 = valid ? __expf(s0 - m0) : 0.f;
        float p1 = valid ? __expf(s1 - m1) : 0.f;
        float p2 = valid ? __expf(s2 - m2) : 0.f;
        float p3 = valid ? __expf(s3 - m3) : 0.f;
        l0 += p0; l1 += p1; l2 += p2; l3 += p3;
        sr01[j] = pk2(p0, p1); sr23[j] = pk2(p2, p3);
    }
#pragma unroll
    for (int o = 16; o; o >>= 1) {
        l0 += __shfl_xor_sync(0xffffffffu, l0, o);
        l1 += __shfl_xor_sync(0xffffffffu, l1, o);
        l2 += __shfl_xor_sync(0xffffffffu, l2, o);
        l3 += __shfl_xor_sync(0xffffffffu, l3, o);
    }

    size_t pb = ((size_t)(head * NRGP + rb * 16 + w) * NSPLIT + split) * 56;
    if (lane == 0) {
        d_P[pb + 52] = pk2(m0, m1);
        d_P[pb + 53] = pk2(m2, m3);
        d_P[pb + 54] = pk2(l0, l1);
        d_P[pb + 55] = pk2(l2, l3);
    }

    // ---- pass 2: partial P @ V per c; value-halving butterfly reduce ------
    bool hi16 = (lane & 16) != 0;
    bool hi8  = (lane & 8) != 0;
#pragma unroll 1
    for (int c = 0; c < 13; ++c) {
        ull ar01 = Z, ar23 = Z, ai01 = Z, ai23 = Z;
        const float4* vp = (const float4*)(vsm + c * KTP + 4 * lane);
        float4 vA = vp[0];
        float4 vB = vp[1];
        float2 v[4] = { make_float2(vA.x, vA.y), make_float2(vA.z, vA.w),
                        make_float2(vB.x, vB.y), make_float2(vB.z, vB.w) };
#pragma unroll
        for (int j = 0; j < 4; ++j) {
            ull vxx = pk2(v[j].x, v[j].x), vyy = pk2(v[j].y, v[j].y);
            ar01 = fma2(sr01[j], vxx, ar01);  ar23 = fma2(sr23[j], vxx, ar23);
            ai01 = fma2(sr01[j], vyy, ai01);  ai23 = fma2(sr23[j], vyy, ai23);
        }
        // stage 1 (xor16): lo keeps rows01, hi keeps rows23
        ull k0 = hi16 ? ar23 : ar01;
        ull k1 = hi16 ? ai23 : ai01;
        ull g0 = hi16 ? ar01 : ar23;
        ull g1 = hi16 ? ai01 : ai23;
        k0 = add2(k0, shfl_xor_ull(g0, 16));
        k1 = add2(k1, shfl_xor_ull(g1, 16));
        // stage 2 (xor8): lo8 keeps re, hi8 keeps im
        ull kk = hi8 ? k1 : k0;
        ull gg = hi8 ? k0 : k1;
        kk = add2(kk, shfl_xor_ull(gg, 8));
        // stages 3-5: plain butterfly on 1 ull
        kk = add2(kk, shfl_xor_ull(kk, 4));
        kk = add2(kk, shfl_xor_ull(kk, 2));
        kk = add2(kk, shfl_xor_ull(kk, 1));
        // octet leaders write: lane 0:{r0,r1} 8:{i0,i1} 16:{r2,r3} 24:{i2,i3}
        if ((lane & 7) == 0)
            d_P[pb + c * 4 + (lane >> 3)] = kk;
    }
}

// ---------------- combine: merge 5 column-split partials -------------------
__global__ void combine_kernel() {
    __shared__ float sbuf[NSPLIT * 112];
    int rg = blockIdx.x;       // 0..135
    int head = blockIdx.y;
    int t = threadIdx.x;

    const ull* P = d_P + (size_t)(head * NRGP + rg) * NSPLIT * 56;
    for (int i = t; i < NSPLIT * 56; i += 128) {
        float a, b;
        upk2(P[i], a, b);
        sbuf[i * 2] = a;
        sbuf[i * 2 + 1] = b;
    }
    __syncthreads();
    if (t >= 104) return;
    int c = t >> 3;
    int comp = (t >> 2) & 1;
    int row = t & 3;

    float M = -1e30f;
#pragma unroll
    for (int k = 0; k < NSPLIT; ++k) M = fmaxf(M, sbuf[k * 112 + 104 + row]);
    float L = 0.f, val = 0.f;
    int fi = (c * 4 + (row >> 1) * 2 + comp) * 2 + (row & 1);
#pragma unroll
    for (int k = 0; k < NSPLIT; ++k) {
        float mk = sbuf[k * 112 + 104 + row];
        float lk = sbuf[k * 112 + 108 + row];
        float s = __expf(mk - M);
        L += lk * s;
        val = fmaf(sbuf[k * 112 + fi], s, val);
    }
    int f = rg * 4 + row;
    if (f < F)
        ((float*)d_O)[(size_t)((head * 13 + c) * F + f) * 2 + comp] = val / L;
}

// ---------------- irfft: Hermitian extend + inverse FFT, real part ---------
__global__ void ifft_kernel(float* __restrict__ out) {
    __shared__ float2 a[1024];
    int sig = blockIdx.x;
    int tid = threadIdx.x;  // 0..511
    const float2* Op = d_O + sig * F;
    float2 o = Op[tid];
    a[__brev(tid) >> 22] = o;
    if (tid > 0) a[__brev(1024 - tid) >> 22] = make_float2(o.x, -o.y);
    if (tid == 0) a[__brev(512) >> 22] = Op[512];
    fft_stages(a, true);
    const float scale = 1.0f / 1024.0f;
    float* op = out + sig * 1024;
    op[tid]       = a[tid].x * scale;
    op[tid + 512] = a[tid + 512].x * scale;
}

// ---------------- launcher --------------------------------------------------
extern "C" void kernel_launch(void* const* d_in, const int* in_sizes, int n_in,
                              void* d_out, int out_size) {
    const float* x  = (const float*)d_in[0];
    const float* wq = (const float*)d_in[1];
    const float* wk = (const float*)d_in[2];
    const float* wv = (const float*)d_in[3];
    float* out = (float*)d_out;

    init_twiddles<<<1, 512>>>();
    fft_forward<<<NSIG, 512>>>(x);
    qkv_kernel<<<dim3(3, H), 256>>>(wq, wk, wv);
    attn_kernel<<<dim3(9 * NSPLIT, H), 512>>>();
    combine_kernel<<<dim3(NRG, H), 128>>>();
    ifft_kernel<<<NSIG, 512>>>(out);
}